// round 5
// baseline (speedup 1.0000x reference)
#include <cuda_runtime.h>
#include <cuda_bf16.h>
#include <cstdint>

#define BB 16
#define CC 512
#define PP 1024
#define OC 1536   // concatenated q|k|v output channels

typedef __nv_bfloat16 bf16;

// ---------------------------------------------------------------------------
// Static device scratch
// ---------------------------------------------------------------------------
__device__ __align__(1024) bf16 g_nT[(size_t)BB * PP * CC];     // [b][p][c]
__device__ __align__(1024) bf16 g_qkvT[(size_t)BB * PP * OC];   // [b][p][o]
__device__ __align__(1024) bf16 g_WT[4 * CC * CC];              // [which][o][c]
__device__ __align__(128)  float g_part[(size_t)BB * 32 * 1024];
__device__ __align__(128)  float g_num[BB * 1024];
__device__ __align__(128)  float g_diag[BB * PP];
__device__ __align__(128)  float g_bcat[OC];

// ---------------------------------------------------------------------------
// helpers
// ---------------------------------------------------------------------------
__device__ __forceinline__ uint32_t smem_u32(const void* p) {
    uint32_t a;
    asm("{ .reg .u64 t; cvta.to.shared.u64 t, %1; cvt.u32.u64 %0, t; }"
        : "=r"(a) : "l"(p));
    return a;
}

#define CPA16(sm, gm) \
    asm volatile("cp.async.cg.shared.global [%0], [%1], 16;" \
                 :: "r"(sm), "l"(gm))

__device__ __forceinline__ void ldsm4(uint32_t* r, uint32_t a) {
    asm volatile("ldmatrix.sync.aligned.m8n8.x4.shared.b16 {%0,%1,%2,%3}, [%4];"
                 : "=r"(r[0]), "=r"(r[1]), "=r"(r[2]), "=r"(r[3]) : "r"(a));
}

__device__ __forceinline__ void mma16816(float* c, const uint32_t* a,
                                         uint32_t b0, uint32_t b1) {
    asm volatile(
        "mma.sync.aligned.m16n8k16.row.col.f32.bf16.bf16.f32 "
        "{%0,%1,%2,%3}, {%4,%5,%6,%7}, {%8,%9}, {%0,%1,%2,%3};"
        : "+f"(c[0]), "+f"(c[1]), "+f"(c[2]), "+f"(c[3])
        : "r"(a[0]), "r"(a[1]), "r"(a[2]), "r"(a[3]), "r"(b0), "r"(b1));
}

// CTA tile 128(M) x 256(N), K-slab 32. smem rows: 64B data + 16B pad.
#define ROWB   80
#define ATILE  (128 * ROWB)          // 10240
#define BTILE  (256 * ROWB)          // 20480
#define STAGE  (ATILE + BTILE)       // 30720
#define SMEM_BYTES (3 * STAGE)       // 92160

// ---------------------------------------------------------------------------
// Weight transpose: WT[o][c] = bf16(W[c][o]); q|k|v|n concat
// ---------------------------------------------------------------------------
__global__ void wt_kernel(const float* __restrict__ Wq, const float* __restrict__ Wk,
                          const float* __restrict__ Wv, const float* __restrict__ Wn,
                          bf16* __restrict__ WT)
{
    const float* srcs[4] = {Wq, Wk, Wv, Wn};
    const float* W = srcs[blockIdx.z];
    bf16* dst = WT + (size_t)blockIdx.z * CC * CC;
    __shared__ float t[32][33];
    int c0 = blockIdx.x * 32, o0 = blockIdx.y * 32;
    for (int i = threadIdx.y; i < 32; i += 8)
        t[i][threadIdx.x] = W[(size_t)(c0 + i) * CC + o0 + threadIdx.x];
    __syncthreads();
    for (int i = threadIdx.y; i < 32; i += 8)
        dst[(size_t)(o0 + i) * CC + c0 + threadIdx.x] =
            __float2bfloat16(t[threadIdx.x][i]);
}

__global__ void bcat_kernel(const float* __restrict__ bq, const float* __restrict__ bk,
                            const float* __restrict__ bv, float* __restrict__ bc)
{
    int i = blockIdx.x * 256 + threadIdx.x;
    if (i < CC) {
        bc[i] = bq[i];
        bc[CC + i] = bk[i];
        bc[2 * CC + i] = bv[i];
    }
}

// ---------------------------------------------------------------------------
// GroupNorm -> transposed bf16 output nT[b][p][c]
// ---------------------------------------------------------------------------
__global__ void gn_kernel(const float* __restrict__ x, bf16* __restrict__ nT)
{
    int b = blockIdx.x >> 5;
    int g = blockIdx.x & 31;
    const float* xp = x + ((size_t)b * CC + g * 16) * PP;

    float s = 0.f, s2 = 0.f;
    for (int i = threadIdx.x; i < 16384; i += 256) {
        float v = xp[i];
        s += v; s2 += v * v;
    }
    __shared__ float sh1[256], sh2[256];
    sh1[threadIdx.x] = s; sh2[threadIdx.x] = s2;
    __syncthreads();
    for (int off = 128; off; off >>= 1) {
        if (threadIdx.x < off) {
            sh1[threadIdx.x] += sh1[threadIdx.x + off];
            sh2[threadIdx.x] += sh2[threadIdx.x + off];
        }
        __syncthreads();
    }
    float mean = sh1[0] * (1.f / 16384.f);
    float var  = sh2[0] * (1.f / 16384.f) - mean * mean;
    float inv  = rsqrtf(var + 1e-5f);

    bf16* np = nT + (size_t)b * PP * CC + g * 16;
    for (int p = threadIdx.x; p < PP; p += 256) {
        uint32_t pk[8];
#pragma unroll
        for (int cc = 0; cc < 16; cc += 2) {
            float v0 = (xp[(size_t)cc * PP + p] - mean) * inv;
            float v1 = (xp[(size_t)(cc + 1) * PP + p] - mean) * inv;
            __nv_bfloat162 h = __floats2bfloat162_rn(v0, v1);
            pk[cc >> 1] = *(uint32_t*)&h;
        }
        uint4* dst = (uint4*)(np + (size_t)p * CC);
        dst[0] = make_uint4(pk[0], pk[1], pk[2], pk[3]);
        dst[1] = make_uint4(pk[4], pk[5], pk[6], pk[7]);
    }
}

// ---------------------------------------------------------------------------
// HMMA GEMM: D[m][n] = sum_{k<512} A[m][k]*B[n][k]
// CTA 128x256, warp 64x64 (2x4 grid), K slab 32, 3-stage cp.async, 1 sync/slab.
// MODE 0: bf16 C[p][o] = D + bias[o], ldc=1536
// MODE 1: fused exp -> g_part / g_num (scores)
// MODE 2: fp32 out[o][p] = x + bias[o] + diag[p]*D, smem-transposed
// ---------------------------------------------------------------------------
template <int MODE>
__global__ __launch_bounds__(256, 1)
void gemm_mma(const bf16* __restrict__ A, long long sA, int ldaA,
              const bf16* __restrict__ Bm, long long sB, int ldaB,
              void* __restrict__ Cout,
              const float* __restrict__ bias, const float* __restrict__ xres,
              const float* __restrict__ dgv,
              float* __restrict__ part, float* __restrict__ num)
{
    extern __shared__ char smem[];
    uint32_t s0 = smem_u32(smem);

    int tid = threadIdx.x, lane = tid & 31, wid = tid >> 5;
    int wm = wid & 1, wn = wid >> 1;        // 2 x 4
    int b = blockIdx.z;
    int m0 = blockIdx.x * 128, n0 = blockIdx.y * 256;

    const char* Ab = (const char*)A + ((size_t)b * sA + (size_t)m0 * ldaA) * 2;
    const char* Bb = (const char*)Bm + ((size_t)b * sB + (size_t)n0 * ldaB) * 2;

    // cp.async mapping: A 512 chunks (2/thread), B 1024 chunks (4/thread)
    uint32_t smA[2], smB[4];
    int gmA[2], gmB[4];
#pragma unroll
    for (int k = 0; k < 2; k++) {
        int ch = tid + k * 256;
        smA[k] = (uint32_t)((ch >> 2) * ROWB + (ch & 3) * 16);
        gmA[k] = (ch >> 2) * ldaA * 2 + (ch & 3) * 16;
    }
#pragma unroll
    for (int k = 0; k < 4; k++) {
        int ch = tid + k * 256;
        smB[k] = (uint32_t)((ch >> 2) * ROWB + (ch & 3) * 16);
        gmB[k] = (ch >> 2) * ldaB * 2 + (ch & 3) * 16;
    }

    // ldmatrix bases
    uint32_t abase, bbase;
    {
        int ar = wm * 64 + (lane & 15);
        int ac = lane >> 4;
        abase = (uint32_t)(ar * ROWB + ac * 16);
        int br = wn * 64 + ((lane >> 4) & 1) * 8 + (lane & 7);
        int bc = (lane >> 3) & 1;
        bbase = (uint32_t)(br * ROWB + bc * 16);
    }

    float acc[4][8][4];
#pragma unroll
    for (int i = 0; i < 4; i++)
#pragma unroll
        for (int j = 0; j < 8; j++)
#pragma unroll
            for (int l = 0; l < 4; l++) acc[i][j][l] = 0.f;

    auto issue = [&](int s, int st) {
        uint32_t ab = s0 + (uint32_t)st * STAGE;
        uint32_t bb = ab + ATILE;
        const char* ga = Ab + s * 64;
        const char* gb = Bb + s * 64;
        CPA16(ab + smA[0], ga + gmA[0]);
        CPA16(ab + smA[1], ga + gmA[1]);
        CPA16(bb + smB[0], gb + gmB[0]);
        CPA16(bb + smB[1], gb + gmB[1]);
        CPA16(bb + smB[2], gb + gmB[2]);
        CPA16(bb + smB[3], gb + gmB[3]);
        asm volatile("cp.async.commit_group;" ::: "memory");
    };

    issue(0, 0);
    issue(1, 1);

    for (int s = 0; s < 16; s++) {
        if (s < 15) asm volatile("cp.async.wait_group 1;" ::: "memory");
        else        asm volatile("cp.async.wait_group 0;" ::: "memory");
        __syncthreads();
        if (s + 2 < 16) issue(s + 2, (s + 2) % 3);

        uint32_t ab = s0 + (uint32_t)(s % 3) * STAGE;
        uint32_t bb = ab + ATILE;

#pragma unroll
        for (int ks = 0; ks < 2; ks++) {
            uint32_t af[4][4], bfr[4][4];
#pragma unroll
            for (int mt = 0; mt < 4; mt++)
                ldsm4(af[mt], ab + abase + mt * (16 * ROWB) + ks * 32);
#pragma unroll
            for (int p = 0; p < 4; p++)
                ldsm4(bfr[p], bb + bbase + p * (16 * ROWB) + ks * 32);
#pragma unroll
            for (int mt = 0; mt < 4; mt++)
#pragma unroll
                for (int nt = 0; nt < 8; nt++)
                    mma16816(acc[mt][nt], af[mt],
                             bfr[nt >> 1][(nt & 1) * 2], bfr[nt >> 1][(nt & 1) * 2 + 1]);
        }
    }

    // ---------------- epilogues ----------------
    int row0 = m0 + wm * 64;
    int col0 = n0 + wn * 64;
    int tr = lane >> 2, tc = (lane & 3) * 2;

    if (MODE == 0) {
        bf16* Cb = (bf16*)Cout + (size_t)b * ((size_t)PP * OC);
#pragma unroll
        for (int mt = 0; mt < 4; mt++) {
            int p1 = row0 + mt * 16 + tr, p2 = p1 + 8;
#pragma unroll
            for (int nt = 0; nt < 8; nt++) {
                int o = col0 + nt * 8 + tc;
                float b0 = bias[o], b1 = bias[o + 1];
                __nv_bfloat162 v01 = __floats2bfloat162_rn(acc[mt][nt][0] + b0,
                                                           acc[mt][nt][1] + b1);
                __nv_bfloat162 v23 = __floats2bfloat162_rn(acc[mt][nt][2] + b0,
                                                           acc[mt][nt][3] + b1);
                *(__nv_bfloat162*)(Cb + (size_t)p1 * OC + o) = v01;
                *(__nv_bfloat162*)(Cb + (size_t)p2 * OC + o) = v23;
            }
        }
    } else if (MODE == 1) {
        const float scale = 0.04419417382415922f;   // 512^-0.5
        __syncthreads();   // before smem reuse
#pragma unroll
        for (int mt = 0; mt < 4; mt++)
#pragma unroll
            for (int nt = 0; nt < 8; nt++)
#pragma unroll
                for (int l = 0; l < 4; l++) {
                    float e = __expf(scale * acc[mt][nt][l]);
                    acc[mt][nt][l] = e;
                    int p = row0 + mt * 16 + tr + ((l >> 1) * 8);
                    int n = col0 + nt * 8 + tc + (l & 1);
                    if (((p >> 5) == (p & 31)) && ((n >> 5) == (n & 31)))
                        num[b * 1024 + (p & 31) * 32 + (n & 31)] = e;
                }
        float* sp = (float*)smem;   // 8 warps x 1024 bins
#pragma unroll
        for (int mtl = 0; mtl < 2; mtl++)
#pragma unroll
            for (int rt = 0; rt < 2; rt++) {
                int i = mtl * 16 + tr + rt * 8;
#pragma unroll
                for (int ntl = 0; ntl < 4; ntl++)
#pragma unroll
                    for (int ct = 0; ct < 2; ct++) {
                        int j = ntl * 8 + tc + ct;
                        int l = rt * 2 + ct;
                        sp[wid * 1024 + i * 32 + j] =
                            acc[mtl][ntl][l] + acc[mtl + 2][ntl][l] +
                            acc[mtl][ntl + 4][l] + acc[mtl + 2][ntl + 4][l];
                    }
            }
        __syncthreads();
        float* pb = part + ((size_t)(b * 32 + blockIdx.y * 8 + blockIdx.x)) * 1024;
        for (int ij = tid; ij < 1024; ij += 256) {
            float sum = 0.f;
#pragma unroll
            for (int w = 0; w < 8; w++) sum += sp[w * 1024 + ij];
            pb[ij] = sum;
        }
    } else {
        float* ob = (float*)Cout + (size_t)b * ((size_t)CC * PP);
        const float* xb = xres + (size_t)b * ((size_t)CC * PP);
        float dgr[4][2];
#pragma unroll
        for (int mt = 0; mt < 4; mt++) {
            dgr[mt][0] = dgv[b * PP + row0 + mt * 16 + tr];
            dgr[mt][1] = dgv[b * PP + row0 + mt * 16 + tr + 8];
        }
        float (*tp)[132] = (float(*)[132])smem;
        for (int h = 0; h < 4; h++) {
            __syncthreads();
            if (wn == h) {
#pragma unroll
                for (int mt = 0; mt < 4; mt++)
#pragma unroll
                    for (int nt = 0; nt < 8; nt++)
#pragma unroll
                        for (int l = 0; l < 4; l++) {
                            int o_in = nt * 8 + tc + (l & 1);
                            int p_l = wm * 64 + mt * 16 + tr + ((l >> 1) * 8);
                            tp[o_in][p_l] = dgr[mt][l >> 1] * acc[mt][nt][l];
                        }
            }
            __syncthreads();
            int r = tid >> 2;
            int cb = (tid & 3) * 32;
            int o = n0 + h * 64 + r;
            float bv = bias[o];
            size_t base = (size_t)o * PP + m0;
#pragma unroll
            for (int k = 0; k < 8; k++) {
                int c = cb + k * 4;
                float4 xv = *(const float4*)(xb + base + c);
                float4 w;
                w.x = xv.x + bv + tp[r][c];
                w.y = xv.y + bv + tp[r][c + 1];
                w.z = xv.z + bv + tp[r][c + 2];
                w.w = xv.w + bv + tp[r][c + 3];
                *(float4*)(ob + base + c) = w;
            }
        }
    }
}

// ---------------------------------------------------------------------------
// diag = num / sum(part)  (fixed-order over 32 tiles -> deterministic)
// ---------------------------------------------------------------------------
__global__ void diag_kernel(const float* __restrict__ part,
                            const float* __restrict__ num,
                            float* __restrict__ diag)
{
    int idx = blockIdx.x * 256 + threadIdx.x;   // 16384 total
    int b = idx >> 10, ij = idx & 1023;
    const float* pp = part + (size_t)b * 32 * 1024 + ij;
    float s = 0.f;
#pragma unroll
    for (int t = 0; t < 32; t++) s += pp[t * 1024];
    diag[idx] = num[idx] / s;
}

// ---------------------------------------------------------------------------
// kernel_launch — inputs: x, Wq, bq, Wk, bk, Wv, bv, Wn, bn
// ---------------------------------------------------------------------------
extern "C" void kernel_launch(void* const* d_in, const int* in_sizes, int n_in,
                              void* d_out, int out_size)
{
    const float* x  = (const float*)d_in[0];
    const float* Wq = (const float*)d_in[1];
    const float* bq = (const float*)d_in[2];
    const float* Wk = (const float*)d_in[3];
    const float* bk = (const float*)d_in[4];
    const float* Wv = (const float*)d_in[5];
    const float* bv = (const float*)d_in[6];
    const float* Wn = (const float*)d_in[7];
    const float* bn = (const float*)d_in[8];
    float* out = (float*)d_out;

    bf16 *pnT, *pqkv, *pWT;
    float *ppart, *pnum, *pdiag, *pbcat;
    cudaGetSymbolAddress((void**)&pnT, g_nT);
    cudaGetSymbolAddress((void**)&pqkv, g_qkvT);
    cudaGetSymbolAddress((void**)&pWT, g_WT);
    cudaGetSymbolAddress((void**)&ppart, g_part);
    cudaGetSymbolAddress((void**)&pnum, g_num);
    cudaGetSymbolAddress((void**)&pdiag, g_diag);
    cudaGetSymbolAddress((void**)&pbcat, g_bcat);

    cudaFuncSetAttribute(gemm_mma<0>, cudaFuncAttributeMaxDynamicSharedMemorySize, SMEM_BYTES);
    cudaFuncSetAttribute(gemm_mma<1>, cudaFuncAttributeMaxDynamicSharedMemorySize, SMEM_BYTES);
    cudaFuncSetAttribute(gemm_mma<2>, cudaFuncAttributeMaxDynamicSharedMemorySize, SMEM_BYTES);

    // 1. Weight transposes + bias concat
    wt_kernel<<<dim3(16, 16, 4), dim3(32, 8)>>>(Wq, Wk, Wv, Wn, pWT);
    bcat_kernel<<<2, 256>>>(bq, bk, bv, pbcat);

    // 2. GroupNorm -> nT bf16
    gn_kernel<<<BB * 32, 256>>>(x, pnT);

    // 3. Merged q|k|v projection
    dim3 gp(8, 6, BB);
    gemm_mma<0><<<gp, 256, SMEM_BYTES>>>(pnT, (long long)PP * CC, CC,
                                         pWT, 0, CC,
                                         pqkv, pbcat, nullptr, nullptr,
                                         nullptr, nullptr);

    // 4. Scores with fused exp epilogue
    dim3 gs(8, 4, BB);
    gemm_mma<1><<<gs, 256, SMEM_BYTES>>>(pqkv, (long long)PP * OC, OC,
                                         pqkv + CC, (long long)PP * OC, OC,
                                         nullptr, nullptr, nullptr, nullptr,
                                         ppart, pnum);

    // 5. diag = num / denom
    diag_kernel<<<64, 256>>>(ppart, pnum, pdiag);

    // 6. Final fused projection
    dim3 gf(8, 2, BB);
    gemm_mma<2><<<gf, 256, SMEM_BYTES>>>(pqkv + 2 * CC, (long long)PP * OC, OC,
                                         pWT + 3 * CC * CC, 0, CC,
                                         out, bn, x, pdiag,
                                         nullptr, nullptr);
}